// round 13
// baseline (speedup 1.0000x reference)
#include <cuda_runtime.h>
#include <cuda_bf16.h>

// HybridQLSTM_65481071409480 — GB300 (sm_103a) — FINAL (converged champion;
// R11/R12 were GPU-acquisition timeouts, kernel never ran — resubmit verbatim)
//
// Algebraic collapse (verified on-HW across 7 passing rounds, rel_err = 0.0
// bit-exact): the reference ends with
//     log_softmax(broadcast_to(expectation[..., None], (S,B,T)), axis=-1)
// over a CONSTANT row of length T=50, which is identically -log(50) for
// every element, independent of ALL inputs (stabilized log_softmax computes
// 0 - log(sum exp 0) = -log 50 bit-exactly in fp32). The embedding gather,
// 512-step LSTM scan, and sin() expectation are dead code. The kernel is a
// 3.125 MiB constant fill of fp32 -log(50).
//
// Convergence (8 measured configs): in-kernel time pinned at ~3.5-3.9us
// (= T_ovh ~5000cyc + CTA ramp; DRAM=0%, writes L2-absorbed, store drain
// ~0.3us) for every shape; body width / guards / grid shape / STG.E.256 all
// <= noise. Champion: 800 CTAs x 256 threads, one guarded float4 store per
// thread. Reproduced: kernel 3.49/3.84us, total 4.608/4.640us, rel_err 0.0.

__global__ __launch_bounds__(256)
void fill_neglog50_kernel(float4* __restrict__ out4, int n4,
                          float* __restrict__ out_tail, int n_tail) {
    const float v = -3.9120230674743652f;  // fp32-nearest -log(50)
    const int idx = blockIdx.x * blockDim.x + threadIdx.x;
    if (idx < n4) {
        out4[idx] = make_float4(v, v, v, v);
    }
    if (idx < n_tail) {                    // n_tail = 0 for this problem
        out_tail[idx] = v;
    }
}

extern "C" void kernel_launch(void* const* d_in, const int* in_sizes, int n_in,
                              void* d_out, int out_size) {
    (void)d_in; (void)in_sizes; (void)n_in;
    if (out_size <= 0) return;

    float* out = (float*)d_out;
    int n4 = out_size >> 2;            // 204800
    int n_tail = out_size & 3;         // 0
    float* tail_ptr = out + (size_t)n4 * 4;

    const int threads = 256;
    int blocks = (n4 + threads - 1) / threads;  // 800
    if (blocks < 1) blocks = 1;

    fill_neglog50_kernel<<<blocks, threads>>>(
        (float4*)out, n4, tail_ptr, n_tail);
}